// round 1
// baseline (speedup 1.0000x reference)
#include <cuda_runtime.h>
#include <cuda_bf16.h>

// Problem constants (fixed by the reference)
#define D_MODEL 1024
#define N_HEAD  16
#define D_K     64
#define BATCH   2
#define SEQ     2048
#define HB      (N_HEAD * BATCH)   // 32 head-batches
#define M_ROWS  (BATCH * SEQ)      // 4096 rows for the projection GEMMs

// Scratch (no cudaMalloc allowed): projected Q/K/V in head-split layout
// [HB, SEQ, D_K] and merged attention output [B, SEQ, D_MODEL].
__device__ float g_qh[HB * SEQ * D_K];
__device__ float g_kh[HB * SEQ * D_K];
__device__ float g_vh[HB * SEQ * D_K];
__device__ float g_ao[BATCH * SEQ * D_MODEL];

// ---------------------------------------------------------------------------
// SGEMM: C = A[M,K] @ B[K,N] + bias[N]
// BM=BN=128, BK=8, 256 threads, 8x8 register micro-tile per thread.
// HEADSPLIT epilogue writes C in [h*BATCH+b, s, dk] layout (dk = n % 64).
// Assumes M,N % 128 == 0, K % 8 == 0 (true here: 4096/1024/1024).
// ---------------------------------------------------------------------------
template <bool HEADSPLIT>
__global__ __launch_bounds__(256)
void sgemm_bias(const float* __restrict__ A, const float* __restrict__ Bm,
                const float* __restrict__ bias, float* __restrict__ C,
                int M, int N, int K)
{
    __shared__ float As[8][128];   // transposed A tile
    __shared__ float Bs[8][128];

    const int tid  = threadIdx.x;
    const int cRow = blockIdx.y;
    const int cCol = blockIdx.x;

    const int innerRowA = tid >> 1;          // 0..127
    const int innerColA = (tid & 1) * 4;     // 0 or 4
    const int innerRowB = tid >> 5;          // 0..7
    const int innerColB = (tid & 31) * 4;    // 0..124

    const int threadRow = tid >> 4;          // 0..15
    const int threadCol = tid & 15;          // 0..15

    const float* Ap = A  + (size_t)cRow * 128 * K;
    const float* Bp = Bm + cCol * 128;

    float acc[8][8];
    #pragma unroll
    for (int i = 0; i < 8; i++)
        #pragma unroll
        for (int j = 0; j < 8; j++) acc[i][j] = 0.0f;

    for (int bk = 0; bk < K; bk += 8) {
        float4 a = *reinterpret_cast<const float4*>(Ap + (size_t)innerRowA * K + innerColA);
        As[innerColA + 0][innerRowA] = a.x;
        As[innerColA + 1][innerRowA] = a.y;
        As[innerColA + 2][innerRowA] = a.z;
        As[innerColA + 3][innerRowA] = a.w;
        *reinterpret_cast<float4*>(&Bs[innerRowB][innerColB]) =
            *reinterpret_cast<const float4*>(Bp + (size_t)innerRowB * N + innerColB);
        __syncthreads();

        Ap += 8;
        Bp += (size_t)8 * N;

        #pragma unroll
        for (int k = 0; k < 8; k++) {
            float regM[8], regN[8];
            #pragma unroll
            for (int i = 0; i < 8; i++) regM[i] = As[k][threadRow * 8 + i];
            #pragma unroll
            for (int j = 0; j < 8; j++) regN[j] = Bs[k][threadCol * 8 + j];
            #pragma unroll
            for (int i = 0; i < 8; i++)
                #pragma unroll
                for (int j = 0; j < 8; j++)
                    acc[i][j] += regM[i] * regN[j];
        }
        __syncthreads();
    }

    #pragma unroll
    for (int i = 0; i < 8; i++) {
        const int m = cRow * 128 + threadRow * 8 + i;
        const int b = m / SEQ;       // used only if HEADSPLIT
        const int s = m % SEQ;
        #pragma unroll
        for (int j = 0; j < 8; j++) {
            const int n = cCol * 128 + threadCol * 8 + j;
            const float v = acc[i][j] + bias[n];
            if (HEADSPLIT) {
                const int h  = n >> 6;      // head = column chunk of 64
                const int dk = n & 63;
                C[(((size_t)(h * BATCH + b) * SEQ + s) << 6) + dk] = v;
            } else {
                C[(size_t)m * N + n] = v;
            }
        }
    }
}

// ---------------------------------------------------------------------------
// Flash-style attention, fp32, thread-per-query-row.
// Grid: (SEQ/128, HB). Block: 128 threads, each owns one query row.
// K/V streamed through smem in tiles of BN keys; scores parked in padded
// smem (conflict-free), online softmax, output written in merged [B,S,D].
// ---------------------------------------------------------------------------
#define ATT_BN 32

__global__ __launch_bounds__(128)
void attn_kernel(const float* __restrict__ Qh, const float* __restrict__ Kh,
                 const float* __restrict__ Vh, float* __restrict__ Out)
{
    __shared__ float Ks[ATT_BN * D_K];           // 8 KB
    __shared__ float Vs[ATT_BN * D_K];           // 8 KB
    __shared__ float Ss[128 * (ATT_BN + 1)];     // ~16.5 KB, pad kills conflicts

    const int tid = threadIdx.x;
    const int hb  = blockIdx.y;
    const int h   = hb / BATCH;
    const int b   = hb % BATCH;
    const int row = blockIdx.x * 128 + tid;      // query row within this hb

    // Load this thread's query row (contiguous 64 floats) into registers.
    float q[D_K];
    const float4* q4 = reinterpret_cast<const float4*>(Qh + ((size_t)hb * SEQ + row) * D_K);
    #pragma unroll
    for (int k = 0; k < 16; k++) {
        float4 t = q4[k];
        q[4 * k + 0] = t.x; q[4 * k + 1] = t.y;
        q[4 * k + 2] = t.z; q[4 * k + 3] = t.w;
    }

    float o[D_K];
    #pragma unroll
    for (int k = 0; k < D_K; k++) o[k] = 0.0f;
    float mrun = -1e30f;
    float lrun = 0.0f;
    const float scale = 0.125f;                  // 1/sqrt(64)

    for (int kt = 0; kt < SEQ; kt += ATT_BN) {
        __syncthreads();
        // Cooperative float4 copy of K/V tiles (contiguous in head-split layout).
        const float4* ksrc = reinterpret_cast<const float4*>(Kh + ((size_t)hb * SEQ + kt) * D_K);
        const float4* vsrc = reinterpret_cast<const float4*>(Vh + ((size_t)hb * SEQ + kt) * D_K);
        float4* kd = reinterpret_cast<float4*>(Ks);
        float4* vd = reinterpret_cast<float4*>(Vs);
        for (int i = tid; i < ATT_BN * 16; i += 128) {
            kd[i] = ksrc[i];
            vd[i] = vsrc[i];
        }
        __syncthreads();

        // Scores for this tile; all threads read the same Ks word -> broadcast.
        float tmax = -1e30f;
        const float4* Ks4 = reinterpret_cast<const float4*>(Ks);
        #pragma unroll 1
        for (int j = 0; j < ATT_BN; j++) {
            float acc = 0.0f;
            #pragma unroll
            for (int k4 = 0; k4 < 16; k4++) {
                float4 kk = Ks4[j * 16 + k4];
                acc += q[4 * k4 + 0] * kk.x + q[4 * k4 + 1] * kk.y
                     + q[4 * k4 + 2] * kk.z + q[4 * k4 + 3] * kk.w;
            }
            float s = acc * scale;
            Ss[tid * (ATT_BN + 1) + j] = s;
            tmax = fmaxf(tmax, s);
        }

        // Online softmax update.
        const float mnew = fmaxf(mrun, tmax);
        const float corr = __expf(mrun - mnew);
        lrun *= corr;
        #pragma unroll
        for (int k = 0; k < D_K; k++) o[k] *= corr;

        const float4* Vs4 = reinterpret_cast<const float4*>(Vs);
        #pragma unroll 1
        for (int j = 0; j < ATT_BN; j++) {
            const float p = __expf(Ss[tid * (ATT_BN + 1) + j] - mnew);
            lrun += p;
            #pragma unroll
            for (int k4 = 0; k4 < 16; k4++) {
                float4 vv = Vs4[j * 16 + k4];
                o[4 * k4 + 0] += p * vv.x;
                o[4 * k4 + 1] += p * vv.y;
                o[4 * k4 + 2] += p * vv.z;
                o[4 * k4 + 3] += p * vv.w;
            }
        }
        mrun = mnew;
    }

    // Normalize and write in merged [B, S, D] layout (column block h*64).
    const float inv = 1.0f / lrun;
    float* outp = Out + ((size_t)(b * SEQ + row)) * D_MODEL + h * D_K;
    #pragma unroll
    for (int k4 = 0; k4 < 16; k4++) {
        float4 t;
        t.x = o[4 * k4 + 0] * inv; t.y = o[4 * k4 + 1] * inv;
        t.z = o[4 * k4 + 2] * inv; t.w = o[4 * k4 + 3] * inv;
        reinterpret_cast<float4*>(outp)[k4] = t;
    }
}

// ---------------------------------------------------------------------------
// Launch. Inputs per reference order:
// 0:q 1:k 2:v 3:w_q 4:b_q 5:w_k 6:b_k 7:w_v 8:b_v 9:w_o 10:b_o
// ---------------------------------------------------------------------------
extern "C" void kernel_launch(void* const* d_in, const int* in_sizes, int n_in,
                              void* d_out, int out_size)
{
    const float* q   = (const float*)d_in[0];
    const float* k   = (const float*)d_in[1];
    const float* v   = (const float*)d_in[2];
    const float* w_q = (const float*)d_in[3];
    const float* b_q = (const float*)d_in[4];
    const float* w_k = (const float*)d_in[5];
    const float* b_k = (const float*)d_in[6];
    const float* w_v = (const float*)d_in[7];
    const float* b_v = (const float*)d_in[8];
    const float* w_o = (const float*)d_in[9];
    const float* b_o = (const float*)d_in[10];
    float* out = (float*)d_out;

    float *qh, *kh, *vh, *ao;
    cudaGetSymbolAddress((void**)&qh, g_qh);
    cudaGetSymbolAddress((void**)&kh, g_kh);
    cudaGetSymbolAddress((void**)&vh, g_vh);
    cudaGetSymbolAddress((void**)&ao, g_ao);

    dim3 gemmGrid(D_MODEL / 128, M_ROWS / 128);   // (8, 32)
    sgemm_bias<true ><<<gemmGrid, 256>>>(q, w_q, b_q, qh, M_ROWS, D_MODEL, D_MODEL);
    sgemm_bias<true ><<<gemmGrid, 256>>>(k, w_k, b_k, kh, M_ROWS, D_MODEL, D_MODEL);
    sgemm_bias<true ><<<gemmGrid, 256>>>(v, w_v, b_v, vh, M_ROWS, D_MODEL, D_MODEL);

    dim3 attnGrid(SEQ / 128, HB);                 // (16, 32)
    attn_kernel<<<attnGrid, 128>>>(qh, kh, vh, ao);

    sgemm_bias<false><<<gemmGrid, 256>>>(ao, w_o, b_o, out, M_ROWS, D_MODEL, D_MODEL);
}

// round 2
// speedup vs baseline: 1.1702x; 1.1702x over previous
#include <cuda_runtime.h>
#include <cuda_bf16.h>

// Problem constants (fixed by the reference)
#define D_MODEL 1024
#define N_HEAD  16
#define D_K     64
#define BATCH   2
#define SEQ     2048
#define HB      (N_HEAD * BATCH)   // 32 head-batches
#define M_ROWS  (BATCH * SEQ)      // 4096 rows for the projection GEMMs

// Scratch (no cudaMalloc allowed)
__device__ float g_qh[HB * SEQ * D_K];
__device__ float g_kh[HB * SEQ * D_K];
__device__ float g_vh[HB * SEQ * D_K];
__device__ float g_ao[BATCH * SEQ * D_MODEL];

// ---------------------------------------------------------------------------
// SGEMM body: C = A[M,K] @ B[K,N] + bias[N]
// BM=BN=128, BK=8, 256 threads, 8x8 register micro-tile per thread.
// ---------------------------------------------------------------------------
template <bool HEADSPLIT>
__device__ __forceinline__
void sgemm_body(const float* __restrict__ A, const float* __restrict__ Bm,
                const float* __restrict__ bias, float* __restrict__ C,
                int M, int N, int K, int cRow, int cCol)
{
    __shared__ float As[8][128];   // transposed A tile
    __shared__ float Bs[8][128];

    const int tid  = threadIdx.x;

    const int innerRowA = tid >> 1;          // 0..127
    const int innerColA = (tid & 1) * 4;     // 0 or 4
    const int innerRowB = tid >> 5;          // 0..7
    const int innerColB = (tid & 31) * 4;    // 0..124

    const int threadRow = tid >> 4;          // 0..15
    const int threadCol = tid & 15;          // 0..15

    const float* Ap = A  + (size_t)cRow * 128 * K;
    const float* Bp = Bm + cCol * 128;

    float acc[8][8];
    #pragma unroll
    for (int i = 0; i < 8; i++)
        #pragma unroll
        for (int j = 0; j < 8; j++) acc[i][j] = 0.0f;

    for (int bk = 0; bk < K; bk += 8) {
        float4 a = *reinterpret_cast<const float4*>(Ap + (size_t)innerRowA * K + innerColA);
        As[innerColA + 0][innerRowA] = a.x;
        As[innerColA + 1][innerRowA] = a.y;
        As[innerColA + 2][innerRowA] = a.z;
        As[innerColA + 3][innerRowA] = a.w;
        *reinterpret_cast<float4*>(&Bs[innerRowB][innerColB]) =
            *reinterpret_cast<const float4*>(Bp + (size_t)innerRowB * N + innerColB);
        __syncthreads();

        Ap += 8;
        Bp += (size_t)8 * N;

        #pragma unroll
        for (int k = 0; k < 8; k++) {
            float regM[8], regN[8];
            #pragma unroll
            for (int i = 0; i < 8; i++) regM[i] = As[k][threadRow * 8 + i];
            #pragma unroll
            for (int j = 0; j < 8; j++) regN[j] = Bs[k][threadCol * 8 + j];
            #pragma unroll
            for (int i = 0; i < 8; i++)
                #pragma unroll
                for (int j = 0; j < 8; j++)
                    acc[i][j] += regM[i] * regN[j];
        }
        __syncthreads();
    }

    #pragma unroll
    for (int i = 0; i < 8; i++) {
        const int m = cRow * 128 + threadRow * 8 + i;
        const int b = m / SEQ;       // used only if HEADSPLIT
        const int s = m % SEQ;
        #pragma unroll
        for (int j = 0; j < 8; j++) {
            const int n = cCol * 128 + threadCol * 8 + j;
            const float v = acc[i][j] + bias[n];
            if (HEADSPLIT) {
                const int h  = n >> 6;      // head = column chunk of 64
                const int dk = n & 63;
                C[(((size_t)(h * BATCH + b) * SEQ + s) << 6) + dk] = v;
            } else {
                C[(size_t)m * N + n] = v;
            }
        }
    }
}

// Fused Q/K/V projection: blockIdx.z selects which projection this CTA does.
__global__ __launch_bounds__(256)
void qkv_gemm(const float* __restrict__ q, const float* __restrict__ k,
              const float* __restrict__ v,
              const float* __restrict__ wq, const float* __restrict__ wk,
              const float* __restrict__ wv,
              const float* __restrict__ bq, const float* __restrict__ bk,
              const float* __restrict__ bv,
              float* __restrict__ qh, float* __restrict__ kh,
              float* __restrict__ vh)
{
    const float *A, *W, *bias;
    float* C;
    if (blockIdx.z == 0)      { A = q; W = wq; bias = bq; C = qh; }
    else if (blockIdx.z == 1) { A = k; W = wk; bias = bk; C = kh; }
    else                      { A = v; W = wv; bias = bv; C = vh; }
    sgemm_body<true>(A, W, bias, C, M_ROWS, D_MODEL, D_MODEL,
                     blockIdx.y, blockIdx.x);
}

__global__ __launch_bounds__(256)
void out_gemm(const float* __restrict__ A, const float* __restrict__ W,
              const float* __restrict__ bias, float* __restrict__ C)
{
    sgemm_body<false>(A, W, bias, C, M_ROWS, D_MODEL, D_MODEL,
                      blockIdx.y, blockIdx.x);
}

// ---------------------------------------------------------------------------
// Flash attention, fp32, register-tiled two-GEMM structure.
// Grid: (SEQ/64, HB). Block: 128 threads (16 rowgroups x 8 cols).
// Each thread: 4x8 micro-tile of S (and of O).
// Smem (dynamic, ~49KB): Qst[d][row] (transposed, prescaled), KV buffer
// (K transposed [d][key], reused for V natural [key][d]), Ps[row][68].
// ---------------------------------------------------------------------------
#define ATT_BQ  64
#define ATT_BKV 64
#define PS_LD   68

#define SM_QST 0
#define SM_KV  (64 * 64)
#define SM_PS  (2 * 64 * 64)
#define ATT_SMEM_FLOATS (2 * 64 * 64 + 64 * PS_LD)

extern __shared__ float att_smem[];

__global__ __launch_bounds__(128, 4)
void attn_kernel(const float* __restrict__ Qh, const float* __restrict__ Kh,
                 const float* __restrict__ Vh, float* __restrict__ Out)
{
    float* Qst = att_smem + SM_QST;   // [64 d][64 row], Q^T * 0.125
    float* KV  = att_smem + SM_KV;    // K^T [64 d][64 key]  OR  V [64 key][64 d]
    float* Ps  = att_smem + SM_PS;    // [64 row][PS_LD]

    const int tid = threadIdx.x;
    const int rg  = tid >> 3;         // 0..15 rowgroup -> rows rg*4..rg*4+3
    const int jc  = tid & 7;          // 0..7  colgroup -> cols jc*8..jc*8+7
    const int hb  = blockIdx.y;
    const int h   = hb / BATCH;
    const int b   = hb % BATCH;
    const int q0  = blockIdx.x * ATT_BQ;

    // ---- Stage Q transposed + prescaled (once per block) ----
    {
        const float4* qsrc = reinterpret_cast<const float4*>(
            Qh + ((size_t)hb * SEQ + q0) * D_K);
        // f: row varies fastest -> smem writes conflict-free (row%32 distinct)
        for (int f = tid; f < 64 * 16; f += 128) {
            int row = f & 63;
            int dch = f >> 6;              // 0..15
            float4 t = qsrc[row * 16 + dch];
            int d4 = dch * 4;
            Qst[(d4 + 0) * 64 + row] = t.x * 0.125f;
            Qst[(d4 + 1) * 64 + row] = t.y * 0.125f;
            Qst[(d4 + 2) * 64 + row] = t.z * 0.125f;
            Qst[(d4 + 3) * 64 + row] = t.w * 0.125f;
        }
    }

    float o[4][8];
    #pragma unroll
    for (int i = 0; i < 4; i++)
        #pragma unroll
        for (int j = 0; j < 8; j++) o[i][j] = 0.0f;
    float mrun[4], lrun[4];
    #pragma unroll
    for (int i = 0; i < 4; i++) { mrun[i] = -1e30f; lrun[i] = 0.0f; }

    for (int kt = 0; kt < SEQ; kt += ATT_BKV) {
        // ---- Stage K tile transposed ----
        __syncthreads();
        {
            const float4* ksrc = reinterpret_cast<const float4*>(
                Kh + ((size_t)hb * SEQ + kt) * D_K);
            for (int f = tid; f < 64 * 16; f += 128) {
                int key = f & 63;
                int dch = f >> 6;
                float4 t = ksrc[key * 16 + dch];
                int d4 = dch * 4;
                KV[(d4 + 0) * 64 + key] = t.x;
                KV[(d4 + 1) * 64 + key] = t.y;
                KV[(d4 + 2) * 64 + key] = t.z;
                KV[(d4 + 3) * 64 + key] = t.w;
            }
        }
        __syncthreads();

        // ---- GEMM1: S[64 rows][64 keys] = (Q*0.125) @ K^T ----
        float s[4][8];
        #pragma unroll
        for (int i = 0; i < 4; i++)
            #pragma unroll
            for (int j = 0; j < 8; j++) s[i][j] = 0.0f;

        #pragma unroll 4
        for (int k = 0; k < D_K; k++) {
            float4 qv = *reinterpret_cast<const float4*>(&Qst[k * 64 + rg * 4]);
            float4 k0 = *reinterpret_cast<const float4*>(&KV[k * 64 + jc * 8]);
            float4 k1 = *reinterpret_cast<const float4*>(&KV[k * 64 + jc * 8 + 4]);
            float rq[4] = {qv.x, qv.y, qv.z, qv.w};
            float rk[8] = {k0.x, k0.y, k0.z, k0.w, k1.x, k1.y, k1.z, k1.w};
            #pragma unroll
            for (int i = 0; i < 4; i++)
                #pragma unroll
                for (int j = 0; j < 8; j++)
                    s[i][j] += rq[i] * rk[j];
        }

        // ---- Online softmax (per row i; replicated across the 8 jc threads) ----
        #pragma unroll
        for (int i = 0; i < 4; i++) {
            float tmax = s[i][0];
            #pragma unroll
            for (int j = 1; j < 8; j++) tmax = fmaxf(tmax, s[i][j]);
            #pragma unroll
            for (int off = 1; off < 8; off <<= 1)
                tmax = fmaxf(tmax, __shfl_xor_sync(0xffffffffu, tmax, off));

            const float mnew = fmaxf(mrun[i], tmax);
            const float corr = __expf(mrun[i] - mnew);
            lrun[i] *= corr;
            #pragma unroll
            for (int j = 0; j < 8; j++) o[i][j] *= corr;

            float rs = 0.0f;
            #pragma unroll
            for (int j = 0; j < 8; j++) {
                float p = __expf(s[i][j] - mnew);
                rs += p;
                Ps[(rg * 4 + i) * PS_LD + jc * 8 + j] = p;
            }
            #pragma unroll
            for (int off = 1; off < 8; off <<= 1)
                rs += __shfl_xor_sync(0xffffffffu, rs, off);
            lrun[i] += rs;
            mrun[i]  = mnew;
        }
        __syncthreads();   // GEMM1 done reading KV; Ps fully written

        // ---- Stage V tile (natural [key][d]) ----
        {
            const float4* vsrc = reinterpret_cast<const float4*>(
                Vh + ((size_t)hb * SEQ + kt) * D_K);
            float4* vd = reinterpret_cast<float4*>(KV);
            for (int f = tid; f < 64 * 16; f += 128) vd[f] = vsrc[f];
        }
        __syncthreads();

        // ---- GEMM2: O += P @ V ----
        #pragma unroll 2
        for (int k = 0; k < ATT_BKV; k += 4) {
            float4 pv[4];
            #pragma unroll
            for (int i = 0; i < 4; i++)
                pv[i] = *reinterpret_cast<const float4*>(
                    &Ps[(rg * 4 + i) * PS_LD + k]);
            #pragma unroll
            for (int kk = 0; kk < 4; kk++) {
                float4 v0 = *reinterpret_cast<const float4*>(&KV[(k + kk) * 64 + jc * 8]);
                float4 v1 = *reinterpret_cast<const float4*>(&KV[(k + kk) * 64 + jc * 8 + 4]);
                float rv[8] = {v0.x, v0.y, v0.z, v0.w, v1.x, v1.y, v1.z, v1.w};
                float rp[4] = {
                    kk == 0 ? pv[0].x : kk == 1 ? pv[0].y : kk == 2 ? pv[0].z : pv[0].w,
                    kk == 0 ? pv[1].x : kk == 1 ? pv[1].y : kk == 2 ? pv[1].z : pv[1].w,
                    kk == 0 ? pv[2].x : kk == 1 ? pv[2].y : kk == 2 ? pv[2].z : pv[2].w,
                    kk == 0 ? pv[3].x : kk == 1 ? pv[3].y : kk == 2 ? pv[3].z : pv[3].w};
                #pragma unroll
                for (int i = 0; i < 4; i++)
                    #pragma unroll
                    for (int j = 0; j < 8; j++)
                        o[i][j] += rp[i] * rv[j];
            }
        }
    }

    // ---- Epilogue: normalize, write merged [B,S,D] layout ----
    #pragma unroll
    for (int i = 0; i < 4; i++) {
        const float inv = 1.0f / lrun[i];
        const int row = q0 + rg * 4 + i;
        float* outp = Out + ((size_t)(b * SEQ + row)) * D_MODEL + h * D_K + jc * 8;
        float4 t0, t1;
        t0.x = o[i][0] * inv; t0.y = o[i][1] * inv;
        t0.z = o[i][2] * inv; t0.w = o[i][3] * inv;
        t1.x = o[i][4] * inv; t1.y = o[i][5] * inv;
        t1.z = o[i][6] * inv; t1.w = o[i][7] * inv;
        reinterpret_cast<float4*>(outp)[0] = t0;
        reinterpret_cast<float4*>(outp)[1] = t1;
    }
}

// ---------------------------------------------------------------------------
// Launch. Inputs per reference order:
// 0:q 1:k 2:v 3:w_q 4:b_q 5:w_k 6:b_k 7:w_v 8:b_v 9:w_o 10:b_o
// ---------------------------------------------------------------------------
extern "C" void kernel_launch(void* const* d_in, const int* in_sizes, int n_in,
                              void* d_out, int out_size)
{
    const float* q   = (const float*)d_in[0];
    const float* k   = (const float*)d_in[1];
    const float* v   = (const float*)d_in[2];
    const float* w_q = (const float*)d_in[3];
    const float* b_q = (const float*)d_in[4];
    const float* w_k = (const float*)d_in[5];
    const float* b_k = (const float*)d_in[6];
    const float* w_v = (const float*)d_in[7];
    const float* b_v = (const float*)d_in[8];
    const float* w_o = (const float*)d_in[9];
    const float* b_o = (const float*)d_in[10];
    float* out = (float*)d_out;

    float *qh, *kh, *vh, *ao;
    cudaGetSymbolAddress((void**)&qh, g_qh);
    cudaGetSymbolAddress((void**)&kh, g_kh);
    cudaGetSymbolAddress((void**)&vh, g_vh);
    cudaGetSymbolAddress((void**)&ao, g_ao);

    const int attSmem = ATT_SMEM_FLOATS * sizeof(float);  // ~49.2 KB
    cudaFuncSetAttribute(attn_kernel,
                         cudaFuncAttributeMaxDynamicSharedMemorySize, attSmem);

    dim3 qkvGrid(D_MODEL / 128, M_ROWS / 128, 3);   // (8, 32, 3)
    qkv_gemm<<<qkvGrid, 256>>>(q, k, v, w_q, w_k, w_v, b_q, b_k, b_v,
                               qh, kh, vh);

    dim3 attnGrid(SEQ / ATT_BQ, HB);                // (32, 32)
    attn_kernel<<<attnGrid, 128, attSmem>>>(qh, kh, vh, ao);

    dim3 gemmGrid(D_MODEL / 128, M_ROWS / 128);     // (8, 32)
    out_gemm<<<gemmGrid, 256>>>(ao, w_o, b_o, out);
}

// round 14
// speedup vs baseline: 5.5110x; 4.7095x over previous
#include <cuda_runtime.h>
#include <cuda_fp16.h>
#include <cstdint>

// Problem constants (fixed by the reference)
#define D_MODEL 1024
#define N_HEAD  16
#define D_K     64
#define BATCH   2
#define SEQ     2048
#define HB      (N_HEAD * BATCH)   // 32 head-batches
#define M_ROWS  (BATCH * SEQ)      // 4096 rows for the projection GEMMs

// Scratch (no cudaMalloc allowed)
__device__ float  g_qh[HB * SEQ * D_K];
__device__ float  g_kh[HB * SEQ * D_K];
__device__ float  g_vh[HB * SEQ * D_K];
__device__ float  g_ao[BATCH * SEQ * D_MODEL];
__device__ __half g_wth[4][D_MODEL * D_MODEL];  // transposed fp16 weights [N][K]

// ---------------------------------------------------------------------------
// fp16 helpers (baseline PTX — no sm_103a-only features)
// ---------------------------------------------------------------------------
__device__ __forceinline__ uint32_t pack_h2(float a, float b) {
    __half2 h = __floats2half2_rn(a, b);
    return *reinterpret_cast<uint32_t*>(&h);
}

__device__ __forceinline__ void mma_h(float c[4], const uint32_t a[4],
                                      const uint32_t b[2]) {
    asm volatile(
        "mma.sync.aligned.m16n8k16.row.col.f32.f16.f16.f32 "
        "{%0,%1,%2,%3}, {%4,%5,%6,%7}, {%8,%9}, {%0,%1,%2,%3};"
        : "+f"(c[0]), "+f"(c[1]), "+f"(c[2]), "+f"(c[3])
        : "r"(a[0]), "r"(a[1]), "r"(a[2]), "r"(a[3]), "r"(b[0]), "r"(b[1]));
}

// ===========================================================================
// fp16 mma.sync GEMM: C[m0:+128, n0:+128] = A[4096,1024] @ Bt^T + bias
// Bt = fp16 [N][K] (pre-transposed weights). 256 threads = 8 warps,
// warp tile 64x32 (4x4 m16n8k16). K-chunk 32 halves, reg-staged dbl buffer.
// Smem row stride 40 halves (20 uints): fragment LDS addr (20g+qd)%32 hits
// all 32 banks (verified).
// ===========================================================================
#define BKH  32
#define SROW 40
#define NCH  (D_MODEL / BKH)   // 32

template <bool HEADSPLIT>
__device__ __forceinline__
void hgemm_body(const float* __restrict__ A, const __half* __restrict__ Bt,
                const float* __restrict__ bias, float* __restrict__ C,
                int m0, int n0)
{
    __shared__ __half As[2][128][SROW];
    __shared__ __half Bs[2][128][SROW];

    const int tid  = threadIdx.x;
    const int wid  = tid >> 5;
    const int lane = tid & 31;
    const int g    = lane >> 2;       // 0..7
    const int qd   = lane & 3;        // 0..3
    const int wm   = (wid & 1) * 64;
    const int wn   = (wid >> 1) * 32;
    const int srow = tid >> 2;        // 0..63 (rows srow, srow+64)
    const int sc8  = (tid & 3) * 8;   // half offset 0/8/16/24

    float acc[4][4][4];
    #pragma unroll
    for (int mt = 0; mt < 4; mt++)
        #pragma unroll
        for (int nt = 0; nt < 4; nt++)
            #pragma unroll
            for (int r = 0; r < 4; r++) acc[mt][nt][r] = 0.0f;

    // ---- prologue: chunk 0 -> buffer 0 ----
    #pragma unroll
    for (int i = 0; i < 2; i++) {
        const int row = srow + i * 64;
        const float* ap = A + (size_t)(m0 + row) * D_MODEL + sc8;
        float4 f0 = *reinterpret_cast<const float4*>(ap);
        float4 f1 = *reinterpret_cast<const float4*>(ap + 4);
        *reinterpret_cast<uint4*>(&As[0][row][sc8]) =
            make_uint4(pack_h2(f0.x, f0.y), pack_h2(f0.z, f0.w),
                       pack_h2(f1.x, f1.y), pack_h2(f1.z, f1.w));
        *reinterpret_cast<uint4*>(&Bs[0][row][sc8]) =
            *reinterpret_cast<const uint4*>(Bt + (size_t)(n0 + row) * D_MODEL + sc8);
    }
    __syncthreads();

    float4 pA[2][2];
    uint4  pB[2];

    #pragma unroll 1
    for (int c = 0; c < NCH; c++) {
        const int buf = c & 1;

        if (c + 1 < NCH) {
            const int kc = (c + 1) * BKH;
            #pragma unroll
            for (int i = 0; i < 2; i++) {
                const int row = srow + i * 64;
                const float* ap = A + (size_t)(m0 + row) * D_MODEL + kc + sc8;
                pA[i][0] = *reinterpret_cast<const float4*>(ap);
                pA[i][1] = *reinterpret_cast<const float4*>(ap + 4);
                pB[i] = *reinterpret_cast<const uint4*>(
                    Bt + (size_t)(n0 + row) * D_MODEL + kc + sc8);
            }
        }

        #pragma unroll
        for (int ks = 0; ks < 2; ks++) {
            uint32_t bf[4][2];
            #pragma unroll
            for (int nt = 0; nt < 4; nt++) {
                const uint32_t* br =
                    reinterpret_cast<const uint32_t*>(&Bs[buf][wn + nt * 8 + g][0]);
                bf[nt][0] = br[ks * 8 + qd];
                bf[nt][1] = br[ks * 8 + qd + 4];
            }
            #pragma unroll
            for (int mt = 0; mt < 4; mt++) {
                const uint32_t* a0 =
                    reinterpret_cast<const uint32_t*>(&As[buf][wm + mt * 16 + g][0]);
                const uint32_t* a8 =
                    reinterpret_cast<const uint32_t*>(&As[buf][wm + mt * 16 + g + 8][0]);
                uint32_t af[4] = {a0[ks * 8 + qd], a8[ks * 8 + qd],
                                  a0[ks * 8 + qd + 4], a8[ks * 8 + qd + 4]};
                #pragma unroll
                for (int nt = 0; nt < 4; nt++)
                    mma_h(acc[mt][nt], af, bf[nt]);
            }
        }

        if (c + 1 < NCH) {
            const int nb = buf ^ 1;
            #pragma unroll
            for (int i = 0; i < 2; i++) {
                const int row = srow + i * 64;
                *reinterpret_cast<uint4*>(&As[nb][row][sc8]) =
                    make_uint4(pack_h2(pA[i][0].x, pA[i][0].y),
                               pack_h2(pA[i][0].z, pA[i][0].w),
                               pack_h2(pA[i][1].x, pA[i][1].y),
                               pack_h2(pA[i][1].z, pA[i][1].w));
                *reinterpret_cast<uint4*>(&Bs[nb][row][sc8]) = pB[i];
            }
            __syncthreads();
        }
    }

    // ---- epilogue: bias add, write (optionally head-split) ----
    #pragma unroll
    for (int mt = 0; mt < 4; mt++) {
        #pragma unroll
        for (int rr = 0; rr < 2; rr++) {
            const int m = m0 + wm + mt * 16 + g + rr * 8;
            int bb = 0, s = 0;
            if (HEADSPLIT) { bb = m >> 11; s = m & 2047; }
            #pragma unroll
            for (int nt = 0; nt < 4; nt++) {
                const int col = n0 + wn + nt * 8 + 2 * qd;
                float2 t;
                t.x = acc[mt][nt][rr * 2 + 0] + bias[col];
                t.y = acc[mt][nt][rr * 2 + 1] + bias[col + 1];
                if (HEADSPLIT) {
                    const int h  = col >> 6;
                    const int dk = col & 63;
                    *reinterpret_cast<float2*>(
                        C + (((size_t)(h * BATCH + bb) * SEQ + s) << 6) + dk) = t;
                } else {
                    *reinterpret_cast<float2*>(C + (size_t)m * D_MODEL + col) = t;
                }
            }
        }
    }
}

__global__ __launch_bounds__(256)
void qkv_gemm_h(const float* __restrict__ q, const float* __restrict__ k,
                const float* __restrict__ v,
                const float* __restrict__ bq, const float* __restrict__ bk,
                const float* __restrict__ bv,
                float* __restrict__ qh, float* __restrict__ kh,
                float* __restrict__ vh)
{
    const float *A, *bias;
    const __half* Bt;
    float* C;
    if (blockIdx.z == 0)      { A = q; Bt = g_wth[0]; bias = bq; C = qh; }
    else if (blockIdx.z == 1) { A = k; Bt = g_wth[1]; bias = bk; C = kh; }
    else                      { A = v; Bt = g_wth[2]; bias = bv; C = vh; }
    hgemm_body<true>(A, Bt, bias, C, blockIdx.y * 128, blockIdx.x * 128);
}

__global__ __launch_bounds__(256)
void out_gemm_h(const float* __restrict__ A, const float* __restrict__ bias,
                float* __restrict__ C)
{
    hgemm_body<false>(A, g_wth[3], bias, C, blockIdx.y * 128, blockIdx.x * 128);
}

// ---------------------------------------------------------------------------
// Weight transpose + fp16 convert: g_wth[z][n*1024 + k] = half(W_z[k][n])
// ---------------------------------------------------------------------------
__global__ __launch_bounds__(256)
void transpose_w(const float* __restrict__ w0, const float* __restrict__ w1,
                 const float* __restrict__ w2, const float* __restrict__ w3)
{
    const float* W = (blockIdx.z == 0) ? w0 : (blockIdx.z == 1) ? w1
                   : (blockIdx.z == 2) ? w2 : w3;
    __half* O = g_wth[blockIdx.z];
    __shared__ float t[32][33];
    const int tx = threadIdx.x, ty = threadIdx.y;
    const int x = blockIdx.x * 32 + tx;
    const int y = blockIdx.y * 32 + ty;
    #pragma unroll
    for (int j = 0; j < 32; j += 8)
        t[ty + j][tx] = W[(size_t)(y + j) * D_MODEL + x];
    __syncthreads();
    const int x2 = blockIdx.y * 32 + tx;
    const int y2 = blockIdx.x * 32 + ty;
    #pragma unroll
    for (int j = 0; j < 32; j += 8)
        O[(size_t)(y2 + j) * D_MODEL + x2] = __float2half_rn(t[tx][ty + j]);
}

// ===========================================================================
// Flash attention, fp16 mma.sync. Grid (SEQ/64, HB), 128 threads (4 warps).
// Warp w owns query rows [w*16, w*16+16). Per tile (64 keys):
//   GEMM1 S = (Q*0.125) @ K^T  (4 k-steps x 8 n-frags)
//   online softmax on fragments; P stays in REGISTERS (the C-fragment cols a
//   thread produces are exactly the A-fragment halves it needs for PV)
//   GEMM2 O += P @ V with V staged transposed [d][key]
// Smem 3 x 64 x 72 halves = 27.6 KB. Row stride 72 halves (36 uints):
// fragment LDS addr (4g+qd)%32 hits all 32 banks.
// ===========================================================================
#define ASR 72

__global__ __launch_bounds__(128)
void attn_mma(const float* __restrict__ Qh, const float* __restrict__ Kh,
              const float* __restrict__ Vh, float* __restrict__ Out)
{
    __shared__ __half Qs[64][ASR];
    __shared__ __half Ks[64][ASR];
    __shared__ __half Vt[64][ASR];   // [d][key]

    const int tid  = threadIdx.x;
    const int wid  = tid >> 5;
    const int lane = tid & 31;
    const int g    = lane >> 2;
    const int qd   = lane & 3;
    const int hb   = blockIdx.y;
    const int h    = hb / BATCH;
    const int b    = hb % BATCH;
    const int q0   = blockIdx.x * 64;
    const int r0   = wid * 16 + g;    // this thread's rows: r0, r0+8

    // ---- stage Q (prescaled by 0.125), once ----
    {
        const float4* qsrc = reinterpret_cast<const float4*>(
            Qh + ((size_t)hb * SEQ + q0) * D_K);
        #pragma unroll
        for (int i = 0; i < 8; i++) {
            const int fidx = tid + i * 128;       // 0..1023
            const int row = fidx >> 4, c4 = fidx & 15;
            float4 t = qsrc[fidx];
            *reinterpret_cast<uint2*>(&Qs[row][c4 * 4]) =
                make_uint2(pack_h2(t.x * 0.125f, t.y * 0.125f),
                           pack_h2(t.z * 0.125f, t.w * 0.125f));
        }
    }
    __syncthreads();

    // hoist Q fragments to registers (reused for all 32 KV tiles)
    uint32_t qf[4][4];
    {
        const uint32_t* q0p = reinterpret_cast<const uint32_t*>(&Qs[r0][0]);
        const uint32_t* q8p = reinterpret_cast<const uint32_t*>(&Qs[r0 + 8][0]);
        #pragma unroll
        for (int ks = 0; ks < 4; ks++) {
            qf[ks][0] = q0p[ks * 8 + qd];
            qf[ks][1] = q8p[ks * 8 + qd];
            qf[ks][2] = q0p[ks * 8 + qd + 4];
            qf[ks][3] = q8p[ks * 8 + qd + 4];
        }
    }

    float o[8][4];
    #pragma unroll
    for (int nt = 0; nt < 8; nt++)
        #pragma unroll
        for (int r = 0; r < 4; r++) o[nt][r] = 0.0f;
    float mrun[2] = {-1e30f, -1e30f};
    float lrun[2] = {0.0f, 0.0f};

    #pragma unroll 1
    for (int kt = 0; kt < SEQ; kt += 64) {
        // ---- stage K [key][d] and V transposed [d][key] ----
        {
            const float4* ksrc = reinterpret_cast<const float4*>(
                Kh + ((size_t)hb * SEQ + kt) * D_K);
            const float4* vsrc = reinterpret_cast<const float4*>(
                Vh + ((size_t)hb * SEQ + kt) * D_K);
            #pragma unroll
            for (int i = 0; i < 8; i++) {
                const int fidx = tid + i * 128;
                const int row = fidx >> 4, c4 = fidx & 15;
                float4 t = ksrc[fidx];
                *reinterpret_cast<uint2*>(&Ks[row][c4 * 4]) =
                    make_uint2(pack_h2(t.x, t.y), pack_h2(t.z, t.w));
                float4 vv = vsrc[fidx];
                Vt[c4 * 4 + 0][row] = __float2half_rn(vv.x);
                Vt[c4 * 4 + 1][row] = __float2half_rn(vv.y);
                Vt[c4 * 4 + 2][row] = __float2half_rn(vv.z);
                Vt[c4 * 4 + 3][row] = __float2half_rn(vv.w);
            }
        }
        __syncthreads();

        // ---- GEMM1: S fragments s[nt][4] ----
        float s[8][4];
        #pragma unroll
        for (int nt = 0; nt < 8; nt++)
            #pragma unroll
            for (int r = 0; r < 4; r++) s[nt][r] = 0.0f;

        #pragma unroll
        for (int ks = 0; ks < 4; ks++) {
            #pragma unroll
            for (int nt = 0; nt < 8; nt++) {
                const uint32_t* kr =
                    reinterpret_cast<const uint32_t*>(&Ks[nt * 8 + g][0]);
                uint32_t bf[2] = {kr[ks * 8 + qd], kr[ks * 8 + qd + 4]};
                mma_h(s[nt], qf[ks], bf);
            }
        }

        // ---- online softmax; P kept in registers as A-fragments ----
        uint32_t preg[8][2];   // preg[j][i]: half2 {P[r0+8i][8j+2qd], +1}
        #pragma unroll
        for (int i = 0; i < 2; i++) {
            float tmax = -1e30f;
            #pragma unroll
            for (int nt = 0; nt < 8; nt++)
                tmax = fmaxf(tmax, fmaxf(s[nt][2 * i], s[nt][2 * i + 1]));
            tmax = fmaxf(tmax, __shfl_xor_sync(0xffffffffu, tmax, 1));
            tmax = fmaxf(tmax, __shfl_xor_sync(0xffffffffu, tmax, 2));

            const float mnew = fmaxf(mrun[i], tmax);
            const float corr = __expf(mrun[i] - mnew);
            #pragma unroll
            for (int nt = 0; nt < 8; nt++) {
                o[nt][2 * i]     *= corr;
                o[nt][2 * i + 1] *= corr;
            }
            float ls = 0.0f;
            #pragma unroll
            for (int nt = 0; nt < 8; nt++) {
                float p0 = __expf(s[nt][2 * i]     - mnew);
                float p1 = __expf(s[nt][2 * i + 1] - mnew);
                ls += p0 + p1;
                preg[nt][i] = pack_h2(p0, p1);
            }
            ls += __shfl_xor_sync(0xffffffffu, ls, 1);
            ls += __shfl_xor_sync(0xffffffffu, ls, 2);
            lrun[i] = lrun[i] * corr + ls;
            mrun[i] = mnew;
        }

        // ---- GEMM2: O += P @ V (A-frags straight from preg) ----
        #pragma unroll
        for (int ks = 0; ks < 4; ks++) {
            uint32_t af[4] = {preg[2 * ks][0],     preg[2 * ks][1],
                              preg[2 * ks + 1][0], preg[2 * ks + 1][1]};
            #pragma unroll
            for (int nt = 0; nt < 8; nt++) {
                const uint32_t* vr =
                    reinterpret_cast<const uint32_t*>(&Vt[nt * 8 + g][0]);
                uint32_t bf[2] = {vr[ks * 8 + qd], vr[ks * 8 + qd + 4]};
                mma_h(o[nt], af, bf);
            }
        }
        __syncthreads();   // protect Ks/Vt before next tile's staging
    }

    // ---- epilogue: normalize, write merged [B,S,D] ----
    #pragma unroll
    for (int i = 0; i < 2; i++) {
        const float inv = 1.0f / lrun[i];
        const int row = q0 + r0 + 8 * i;
        float* outp = Out + ((size_t)(b * SEQ + row)) * D_MODEL + h * D_K;
        #pragma unroll
        for (int nt = 0; nt < 8; nt++) {
            float2 t;
            t.x = o[nt][2 * i]     * inv;
            t.y = o[nt][2 * i + 1] * inv;
            *reinterpret_cast<float2*>(outp + nt * 8 + 2 * qd) = t;
        }
    }
}

// ---------------------------------------------------------------------------
// Launch. Inputs per reference order:
// 0:q 1:k 2:v 3:w_q 4:b_q 5:w_k 6:b_k 7:w_v 8:b_v 9:w_o 10:b_o
// ---------------------------------------------------------------------------
extern "C" void kernel_launch(void* const* d_in, const int* in_sizes, int n_in,
                              void* d_out, int out_size)
{
    const float* q   = (const float*)d_in[0];
    const float* k   = (const float*)d_in[1];
    const float* v   = (const float*)d_in[2];
    const float* w_q = (const float*)d_in[3];
    const float* b_q = (const float*)d_in[4];
    const float* w_k = (const float*)d_in[5];
    const float* b_k = (const float*)d_in[6];
    const float* w_v = (const float*)d_in[7];
    const float* b_v = (const float*)d_in[8];
    const float* w_o = (const float*)d_in[9];
    const float* b_o = (const float*)d_in[10];
    float* out = (float*)d_out;

    float *qh, *kh, *vh, *ao;
    cudaGetSymbolAddress((void**)&qh, g_qh);
    cudaGetSymbolAddress((void**)&kh, g_kh);
    cudaGetSymbolAddress((void**)&vh, g_vh);
    cudaGetSymbolAddress((void**)&ao, g_ao);

    // 1) transpose + fp16-convert all four weight matrices
    dim3 trGrid(D_MODEL / 32, D_MODEL / 32, 4);
    transpose_w<<<trGrid, dim3(32, 8)>>>(w_q, w_k, w_v, w_o);

    // 2) fused Q/K/V projections (fp16 mma.sync)
    dim3 qkvGrid(D_MODEL / 128, M_ROWS / 128, 3);   // (8, 32, 3)
    qkv_gemm_h<<<qkvGrid, 256>>>(q, k, v, b_q, b_k, b_v, qh, kh, vh);

    // 3) attention (fp16 mma.sync flash)
    dim3 attnGrid(SEQ / 64, HB);                    // (32, 32)
    attn_mma<<<attnGrid, 128>>>(qh, kh, vh, ao);

    // 4) output projection (fp16 mma.sync)
    dim3 oGrid(D_MODEL / 128, M_ROWS / 128);        // (8, 32)
    out_gemm_h<<<oGrid, 256>>>(ao, b_o, out);
}